// round 2
// baseline (speedup 1.0000x reference)
#include <cuda_runtime.h>

#define D_IN   1024
#define D_FEAT 4096
#define DEG    4
#define RPB    8          // rows per block

// Table layout (per degree d, region of 8192 floats):
//   phys = d*8192 + idx*8 + (r ^ ((idx>>2)&7))
// - XOR swizzle keeps aligned row-PAIRS aligned -> LDS.64 gather works.
// - Table STS (warp owns row r, lanes sweep i=k*32+lane) is conflict-free.
// Phase-1 scratch (32x32 transpose) reuses the table region: warp (d,r)
// uses floats [d*8192 + r*1024, +1024) before the table is written.

__global__ __launch_bounds__(1024, 1)
void srht_kernel(const float* __restrict__ x,
                 const float* __restrict__ rad,
                 const int*   __restrict__ perm,
                 const float* __restrict__ log_ls,
                 const float* __restrict__ log_var,
                 float* __restrict__ out)
{
    extern __shared__ float sw[];   // DEG * 8192 floats = 128 KB

    const int tid  = threadIdx.x;
    const int wid  = tid >> 5;
    const int lane = tid & 31;
    const int row0 = blockIdx.x * RPB;

    const float inv_ls = expf(-log_ls[0]);

    // ---------------- Phase 1: FWHT, no shuffles ----------------
    {
        const int d = wid >> 3;     // 0..3
        const int r = wid & 7;      // 0..7
        // lane holds j = lane*32 + k  (j low 5 bits = k -> in-register)
        const float4* __restrict__ xr4 =
            (const float4*)(x + (size_t)(row0 + r) * D_IN + lane * 32);
        const float4* __restrict__ rd4 =
            (const float4*)(rad + d * D_IN + lane * 32);

        float v[32];
        #pragma unroll
        for (int c = 0; c < 8; c++) {
            float4 xv = xr4[c];
            float4 rv = rd4[c];
            v[4*c+0] = xv.x * rv.x * inv_ls;
            v[4*c+1] = xv.y * rv.y * inv_ls;
            v[4*c+2] = xv.z * rv.z * inv_ls;
            v[4*c+3] = xv.w * rv.w * inv_ls;
        }

        // stages h = 1,2,4,8,16 (bits of k) in registers
        #pragma unroll
        for (int mb = 0; mb < 5; mb++) {
            const int m = 1 << mb;
            #pragma unroll
            for (int k = 0; k < 32; k++) {
                if ((k & m) == 0) {
                    float a = v[k], b = v[k + m];
                    v[k] = a + b;  v[k + m] = a - b;
                }
            }
        }

        // 32x32 transpose through warp-private scratch (inside table region d)
        float* __restrict__ scr = sw + wid * 1024;   // == d*8192 + r*1024
        // STS.128, 16B-group xor swizzle: conflict-free
        #pragma unroll
        for (int c = 0; c < 8; c++) {
            *(float4*)(scr + lane * 32 + ((c ^ (lane & 7)) << 2)) =
                make_float4(v[4*c+0], v[4*c+1], v[4*c+2], v[4*c+3]);
        }
        __syncwarp();
        // transposed scalar LDS: v[k] = element j = k*32 + lane ; conflict-free
        const int l2 = lane >> 2;
        const int l3 = lane & 3;
        #pragma unroll
        for (int k = 0; k < 32; k++) {
            v[k] = scr[k * 32 + ((l2 ^ (k & 7)) << 2) + l3];
        }

        // stages h = 32..512 (bits of k after transpose) in registers
        #pragma unroll
        for (int mb = 0; mb < 5; mb++) {
            const int m = 1 << mb;
            #pragma unroll
            for (int k = 0; k < 32; k++) {
                if ((k & m) == 0) {
                    float a = v[k], b = v[k + m];
                    v[k] = a + b;  v[k + m] = a - b;
                }
            }
        }

        // all scratch reads must complete before table writes clobber them
        __syncthreads();

        float* __restrict__ swd = sw + d * (D_IN * RPB);
        #pragma unroll
        for (int k = 0; k < 32; k++) {
            int i = k * 32 + lane;
            swd[i * 8 + (r ^ ((i >> 2) & 7))] = v[k];
        }
    }
    __syncthreads();

    // --------- Phase 2: pair-gather (LDS.64) + product + STG.64 ---------
    // lane = rp*8 + fi : rows 2rp, 2rp+1 ; features fbase, fbase+1
    const float oscale = expf(0.5f * log_var[0]) * (1.0f / 64.0f);
    const int rp = lane >> 3;      // 0..3
    const int fi = lane & 7;       // 0..7
    const int rlo = 2 * rp;

    float* __restrict__ out_lo = out + (size_t)(row0 + rlo)     * D_FEAT;
    float* __restrict__ out_hi = out + (size_t)(row0 + rlo + 1) * D_FEAT;

    #pragma unroll
    for (int it = 0; it < 8; it++) {
        const int fbase = it * 512 + wid * 16 + fi * 2;
        float aAlo = oscale, aAhi = oscale, aBlo = oscale, aBhi = oscale;
        #pragma unroll
        for (int d = 0; d < DEG; d++) {
            const int2 p = *(const int2*)(perm + d * D_FEAT + fbase);
            const float* __restrict__ swd = sw + d * (D_IN * RPB);

            // feature A
            {
                const int c  = (p.x >> 2) & 7;
                const int pb = (rlo ^ c) & 6;
                float2 q = *(const float2*)(swd + p.x * 8 + pb);
                float lo = (c & 1) ? q.y : q.x;
                float hi = (c & 1) ? q.x : q.y;
                aAlo *= lo;  aAhi *= hi;
            }
            // feature B
            {
                const int c  = (p.y >> 2) & 7;
                const int pb = (rlo ^ c) & 6;
                float2 q = *(const float2*)(swd + p.y * 8 + pb);
                float lo = (c & 1) ? q.y : q.x;
                float hi = (c & 1) ? q.x : q.y;
                aBlo *= lo;  aBhi *= hi;
            }
        }
        *(float2*)(out_lo + fbase) = make_float2(aAlo, aBlo);
        *(float2*)(out_hi + fbase) = make_float2(aAhi, aBhi);
    }
}

extern "C" void kernel_launch(void* const* d_in, const int* in_sizes, int n_in,
                              void* d_out, int out_size)
{
    const float* x   = (const float*)d_in[0];
    const float* rad = (const float*)d_in[1];
    const int*   pm  = (const int*)d_in[2];
    const float* lls = (const float*)d_in[3];
    const float* lv  = (const float*)d_in[4];
    float* out = (float*)d_out;

    const int rows = in_sizes[0] / D_IN;                     // 16384
    const int smem = DEG * D_IN * RPB * (int)sizeof(float);  // 131072 B

    cudaFuncSetAttribute(srht_kernel,
                         cudaFuncAttributeMaxDynamicSharedMemorySize, smem);
    srht_kernel<<<rows / RPB, 1024, smem>>>(x, rad, pm, lls, lv, out);
}